// round 13
// baseline (speedup 1.0000x reference)
#include <cuda_runtime.h>
#include <stdint.h>

#define HDIM 256
#define TS   256
#define BTOT 4096
#define BC   14
#define NP   7
#define NBLK ((BTOT + BC - 1) / BC)   // 293

// Repacked W: g_Wp[h4*256 + g] = float4{ W[g][4h4 .. 4h4+3] }  (coalesced across g)
__device__ float4 g_Wp[64 * 256];

__global__ void pack_w_kernel(const float* __restrict__ W) {
    int idx = blockIdx.x * blockDim.x + threadIdx.x;   // 0..16383
    int h4 = idx >> 8, gg = idx & 255;
    const float4* Wv = (const float4*)W;
    g_Wp[idx] = Wv[gg * 64 + h4];
}

// Threefry-2x32, 20 rounds — matches jax._src.prng.threefry2x32 exactly.
__device__ __forceinline__ uint2 tf2x32(uint32_t k0, uint32_t k1, uint32_t c0, uint32_t c1) {
    uint32_t ks2 = k0 ^ k1 ^ 0x1BD11BDAu;
    uint32_t x0 = c0 + k0, x1 = c1 + k1;
#define TFR(r) { x0 += x1; x1 = __funnelshift_l(x1, x1, r); x1 ^= x0; }
    TFR(13) TFR(15) TFR(26) TFR(6)
    x0 += k1;  x1 += ks2 + 1u;
    TFR(17) TFR(29) TFR(16) TFR(24)
    x0 += ks2; x1 += k0 + 2u;
    TFR(13) TFR(15) TFR(26) TFR(6)
    x0 += k0;  x1 += k1 + 3u;
    TFR(17) TFR(29) TFR(16) TFR(24)
    x0 += k1;  x1 += ks2 + 4u;
    TFR(13) TFR(15) TFR(26) TFR(6)
    x0 += ks2; x1 += k0 + 5u;
#undef TFR
    return make_uint2(x0, x1);
}

// jax.random.normal, threefry-partitionable path (default since JAX 0.4.36):
// bits[j] = x0 ^ x1 of threefry(key, (hi=0, lo=j)); uniform in [nextafter(-1,0), 1); sqrt(2)*erfinv.
__device__ __forceinline__ float jax_normal(uint2 key, uint32_t j) {
    uint2 r = tf2x32(key.x, key.y, 0u, j);
    uint32_t bits = r.x ^ r.y;
    float f = __uint_as_float((bits >> 9) | 0x3F800000u) - 1.0f;
    const float LO = -0.99999994f;               // nextafter(-1, 0)
    float u = fmaxf(LO, fmaf(f, 2.0f, LO));      // (hi-lo) rounds to 2.0f in fp32
    return 1.41421356f * erfinvf(u);
}

#define FMA2(d, a, b)     asm("fma.rn.f32x2 %0, %1, %2, %0;" : "+l"(d) : "l"(a), "l"(b))
#define PACK2(out, lo, hi) asm("mov.b64 %0, {%1, %2};" : "=l"(out) : "r"(lo), "r"(hi))
#define UNPACK2(lo, hi, in) asm("mov.b64 {%0, %1}, %2;" : "=r"(lo), "=r"(hi) : "l"(in))

__global__ __launch_bounds__(256, 2)
void drnet_kernel(const float* __restrict__ img, const float* __restrict__ W_ih,
                  const float* __restrict__ b_ih, const float* __restrict__ b_hh,
                  float* __restrict__ out) {
    // latent stored pair-interleaved for packed f32x2 math: Lp[p][h][j] = latent[2p+j][h]
    __shared__ __align__(16) float Lp[NP][HDIM][2];
    __shared__ float Xs[BC][TS];
    __shared__ uint2 Ks[TS];

    const int g = threadIdx.x;          // output feature
    const int base = blockIdx.x * BC;   // first batch row of this CTA

    // per-step keys: key_t = threefry((0,42), (0,t))  [partitionable split]
    Ks[g] = tf2x32(0u, 42u, 0u, (uint32_t)g);

    #pragma unroll
    for (int i = 0; i < BC; ++i) {
        int b = base + i; if (b >= BTOT) b = BTOT - 1;   // clamp (dupes never stored)
        Xs[i][g] = img[b * TS + g];                       // coalesced (g == t index here)
    }
    #pragma unroll
    for (int p = 0; p < NP; ++p) { Lp[p][g][0] = 0.f; Lp[p][g][1] = 0.f; }

    const float wih  = W_ih[g];
    const float bsum = b_ih[g] + b_hh[g];
    __syncthreads();

    for (int t = 0; t < TS; ++t) {
        const float a = (float)(257 - t) / 257.0f;        // a_t = (T - t + 1)/(T+1)
        const float sigma = sqrtf(a * (1.0f - a));
        const uint2 key = Ks[t];

        // acc[p] holds {arg(2p), arg(2p+1)} packed; init = x*w_ih + (b_ih + b_hh)
        unsigned long long acc[NP];
        #pragma unroll
        for (int p = 0; p < NP; ++p) {
            float alo = fmaf(Xs[2*p][t],   wih, bsum);
            float ahi = fmaf(Xs[2*p+1][t], wih, bsum);
            PACK2(acc[p], __float_as_uint(alo), __float_as_uint(ahi));
        }

        // matvec: acc[p] += sum_h W[g][h] * latent[{2p,2p+1}][h]  via packed fma.rn.f32x2
        float4 w4 = g_Wp[g];
        #pragma unroll 2
        for (int h4 = 0; h4 < 64; ++h4) {
            float4 wn = g_Wp[(((h4 + 1) & 63) << 8) + g];   // prefetch next
            unsigned long long wx, wy, wz, ww;
            PACK2(wx, __float_as_uint(w4.x), __float_as_uint(w4.x));
            PACK2(wy, __float_as_uint(w4.y), __float_as_uint(w4.y));
            PACK2(wz, __float_as_uint(w4.z), __float_as_uint(w4.z));
            PACK2(ww, __float_as_uint(w4.w), __float_as_uint(w4.w));
            #pragma unroll
            for (int p = 0; p < NP; ++p) {
                const ulonglong2* lp = (const ulonglong2*)&Lp[p][h4 * 4][0]; // broadcast LDS
                ulonglong2 l01 = lp[0];   // pairs for h=4h4, 4h4+1
                ulonglong2 l23 = lp[1];   // pairs for h=4h4+2, 4h4+3
                FMA2(acc[p], wx, l01.x);
                FMA2(acc[p], wy, l01.y);
                FMA2(acc[p], wz, l23.x);
                FMA2(acc[p], ww, l23.y);
            }
            w4 = wn;
        }

        // tanh + noise (does not touch Lp)
        float hv[BC], nz[BC];
        #pragma unroll
        for (int p = 0; p < NP; ++p) {
            uint32_t alo, ahi;
            UNPACK2(alo, ahi, acc[p]);
            hv[2*p]   = tanhf(__uint_as_float(alo));
            hv[2*p+1] = tanhf(__uint_as_float(ahi));
            nz[2*p]   = jax_normal(key, (uint32_t)((base + 2*p)     * HDIM + g));
            nz[2*p+1] = jax_normal(key, (uint32_t)((base + 2*p + 1) * HDIM + g));
        }

        __syncthreads();   // all matvec reads of Lp complete before updates
        #pragma unroll
        for (int p = 0; p < NP; ++p) {
            // latent = ((latent + x) + h) + sigma * (0.1 * normal)  — reference op order
            float l0 = Lp[p][g][0], l1 = Lp[p][g][1];
            l0 = l0 + Xs[2*p][t];   l0 = l0 + hv[2*p];   l0 = l0 + sigma * (0.1f * nz[2*p]);
            l1 = l1 + Xs[2*p+1][t]; l1 = l1 + hv[2*p+1]; l1 = l1 + sigma * (0.1f * nz[2*p+1]);
            Lp[p][g][0] = l0; Lp[p][g][1] = l1;
        }
        __syncthreads();   // updates visible before next step's matvec
    }

    #pragma unroll
    for (int p = 0; p < NP; ++p) {
        int b0 = base + 2*p, b1 = b0 + 1;
        if (b0 < BTOT) out[b0 * HDIM + g] = Lp[p][g][0];
        if (b1 < BTOT) out[b1 * HDIM + g] = Lp[p][g][1];
    }
}

extern "C" void kernel_launch(void* const* d_in, const int* in_sizes, int n_in,
                              void* d_out, int out_size) {
    // metadata order: T (int scalar), flat_img, W_ih, W_hh, b_ih, b_hh.
    // Be robust to T being absent: last 5 inputs are the arrays.
    int o = (n_in >= 6) ? (n_in - 5) : 0;
    const float* img  = (const float*)d_in[o + 0];
    const float* W_ih = (const float*)d_in[o + 1];
    const float* W_hh = (const float*)d_in[o + 2];
    const float* b_ih = (const float*)d_in[o + 3];
    const float* b_hh = (const float*)d_in[o + 4];

    pack_w_kernel<<<64, 256>>>(W_hh);
    drnet_kernel<<<NBLK, 256>>>(img, W_ih, b_ih, b_hh, (float*)d_out);
}

// round 14
// speedup vs baseline: 1.0540x; 1.0540x over previous
#include <cuda_runtime.h>
#include <stdint.h>

#define HDIM 256
#define TS   256
#define BTOT 4096
#define BC   14
#define NP   7
#define NBLK ((BTOT + BC - 1) / BC)   // 293

// Repacked W: g_Wp[h4*256 + g] = float4{ W[g][4h4 .. 4h4+3] }  (coalesced across g)
__device__ float4 g_Wp[64 * 256];

__global__ void pack_w_kernel(const float* __restrict__ W) {
    int idx = blockIdx.x * blockDim.x + threadIdx.x;   // 0..16383
    int h4 = idx >> 8, gg = idx & 255;
    const float4* Wv = (const float4*)W;
    g_Wp[idx] = Wv[gg * 64 + h4];
}

// Threefry-2x32, 20 rounds — matches jax._src.prng.threefry2x32 exactly.
__device__ __forceinline__ uint2 tf2x32(uint32_t k0, uint32_t k1, uint32_t c0, uint32_t c1) {
    uint32_t ks2 = k0 ^ k1 ^ 0x1BD11BDAu;
    uint32_t x0 = c0 + k0, x1 = c1 + k1;
#define TFR(r) { x0 += x1; x1 = __funnelshift_l(x1, x1, r); x1 ^= x0; }
    TFR(13) TFR(15) TFR(26) TFR(6)
    x0 += k1;  x1 += ks2 + 1u;
    TFR(17) TFR(29) TFR(16) TFR(24)
    x0 += ks2; x1 += k0 + 2u;
    TFR(13) TFR(15) TFR(26) TFR(6)
    x0 += k0;  x1 += k1 + 3u;
    TFR(17) TFR(29) TFR(16) TFR(24)
    x0 += k1;  x1 += ks2 + 4u;
    TFR(13) TFR(15) TFR(26) TFR(6)
    x0 += ks2; x1 += k0 + 5u;
#undef TFR
    return make_uint2(x0, x1);
}

// jax.random.normal, threefry-partitionable path (default since JAX 0.4.36):
// bits[j] = x0 ^ x1 of threefry(key, (hi=0, lo=j)); uniform in [nextafter(-1,0), 1); sqrt(2)*erfinv.
__device__ __forceinline__ float jax_normal(uint2 key, uint32_t j) {
    uint2 r = tf2x32(key.x, key.y, 0u, j);
    uint32_t bits = r.x ^ r.y;
    float f = __uint_as_float((bits >> 9) | 0x3F800000u) - 1.0f;
    const float LO = -0.99999994f;               // nextafter(-1, 0)
    float u = fmaxf(LO, fmaf(f, 2.0f, LO));      // (hi-lo) rounds to 2.0f in fp32
    return 1.41421356f * erfinvf(u);
}

#define FMA2(d, a, b)     asm("fma.rn.f32x2 %0, %1, %2, %0;" : "+l"(d) : "l"(a), "l"(b))
#define PACK2(out, lo, hi) asm("mov.b64 %0, {%1, %2};" : "=l"(out) : "r"(lo), "r"(hi))
#define UNPACK2(lo, hi, in) asm("mov.b64 {%0, %1}, %2;" : "=r"(lo), "=r"(hi) : "l"(in))

__global__ __launch_bounds__(256, 2)
void drnet_kernel(const float* __restrict__ img, const float* __restrict__ W_ih,
                  const float* __restrict__ b_ih, const float* __restrict__ b_hh,
                  float* __restrict__ out) {
    // latent stored pair-interleaved for packed f32x2 math: Lp[p][h][j] = latent[2p+j][h]
    __shared__ __align__(16) float Lp[NP][HDIM][2];
    __shared__ float Xs[BC][TS];
    __shared__ uint2 Ks[TS];

    const int g = threadIdx.x;          // output feature
    const int base = blockIdx.x * BC;   // first batch row of this CTA

    // per-step keys: key_t = threefry((0,42), (0,t))  [partitionable split]
    Ks[g] = tf2x32(0u, 42u, 0u, (uint32_t)g);

    #pragma unroll
    for (int i = 0; i < BC; ++i) {
        int b = base + i; if (b >= BTOT) b = BTOT - 1;   // clamp (dupes never stored)
        Xs[i][g] = img[b * TS + g];                       // coalesced (g == t index here)
    }
    #pragma unroll
    for (int p = 0; p < NP; ++p) { Lp[p][g][0] = 0.f; Lp[p][g][1] = 0.f; }

    const float wih  = W_ih[g];
    const float bsum = b_ih[g] + b_hh[g];
    __syncthreads();

    for (int t = 0; t < TS; ++t) {
        const float a = (float)(257 - t) / 257.0f;        // a_t = (T - t + 1)/(T+1)
        const float sigma = sqrtf(a * (1.0f - a));
        const uint2 key = Ks[t];

        // acc[p] holds {arg(2p), arg(2p+1)} packed; init = x*w_ih + (b_ih + b_hh)
        unsigned long long acc[NP];
        #pragma unroll
        for (int p = 0; p < NP; ++p) {
            float alo = fmaf(Xs[2*p][t],   wih, bsum);
            float ahi = fmaf(Xs[2*p+1][t], wih, bsum);
            PACK2(acc[p], __float_as_uint(alo), __float_as_uint(ahi));
        }

        // matvec: acc[p] += sum_h W[g][h] * latent[{2p,2p+1}][h]  via packed fma.rn.f32x2
        float4 w4 = g_Wp[g];
        #pragma unroll 2
        for (int h4 = 0; h4 < 64; ++h4) {
            float4 wn = g_Wp[(((h4 + 1) & 63) << 8) + g];   // prefetch next
            unsigned long long wx, wy, wz, ww;
            PACK2(wx, __float_as_uint(w4.x), __float_as_uint(w4.x));
            PACK2(wy, __float_as_uint(w4.y), __float_as_uint(w4.y));
            PACK2(wz, __float_as_uint(w4.z), __float_as_uint(w4.z));
            PACK2(ww, __float_as_uint(w4.w), __float_as_uint(w4.w));
            #pragma unroll
            for (int p = 0; p < NP; ++p) {
                const ulonglong2* lp = (const ulonglong2*)&Lp[p][h4 * 4][0]; // broadcast LDS
                ulonglong2 l01 = lp[0];   // pairs for h=4h4, 4h4+1
                ulonglong2 l23 = lp[1];   // pairs for h=4h4+2, 4h4+3
                FMA2(acc[p], wx, l01.x);
                FMA2(acc[p], wy, l01.y);
                FMA2(acc[p], wz, l23.x);
                FMA2(acc[p], ww, l23.y);
            }
            w4 = wn;
        }

        // tanh + noise (does not touch Lp)
        float hv[BC], nz[BC];
        #pragma unroll
        for (int p = 0; p < NP; ++p) {
            uint32_t alo, ahi;
            UNPACK2(alo, ahi, acc[p]);
            hv[2*p]   = tanhf(__uint_as_float(alo));
            hv[2*p+1] = tanhf(__uint_as_float(ahi));
            nz[2*p]   = jax_normal(key, (uint32_t)((base + 2*p)     * HDIM + g));
            nz[2*p+1] = jax_normal(key, (uint32_t)((base + 2*p + 1) * HDIM + g));
        }

        __syncthreads();   // all matvec reads of Lp complete before updates
        #pragma unroll
        for (int p = 0; p < NP; ++p) {
            // latent = ((latent + x) + h) + sigma * (0.1 * normal)  — reference op order
            float l0 = Lp[p][g][0], l1 = Lp[p][g][1];
            l0 = l0 + Xs[2*p][t];   l0 = l0 + hv[2*p];   l0 = l0 + sigma * (0.1f * nz[2*p]);
            l1 = l1 + Xs[2*p+1][t]; l1 = l1 + hv[2*p+1]; l1 = l1 + sigma * (0.1f * nz[2*p+1]);
            Lp[p][g][0] = l0; Lp[p][g][1] = l1;
        }
        __syncthreads();   // updates visible before next step's matvec
    }

    #pragma unroll
    for (int p = 0; p < NP; ++p) {
        int b0 = base + 2*p, b1 = b0 + 1;
        if (b0 < BTOT) out[b0 * HDIM + g] = Lp[p][g][0];
        if (b1 < BTOT) out[b1 * HDIM + g] = Lp[p][g][1];
    }
}

extern "C" void kernel_launch(void* const* d_in, const int* in_sizes, int n_in,
                              void* d_out, int out_size) {
    // metadata order: T (int scalar), flat_img, W_ih, W_hh, b_ih, b_hh.
    // Be robust to T being absent: last 5 inputs are the arrays.
    int o = (n_in >= 6) ? (n_in - 5) : 0;
    const float* img  = (const float*)d_in[o + 0];
    const float* W_ih = (const float*)d_in[o + 1];
    const float* W_hh = (const float*)d_in[o + 2];
    const float* b_ih = (const float*)d_in[o + 3];
    const float* b_hh = (const float*)d_in[o + 4];

    pack_w_kernel<<<64, 256>>>(W_hh);
    drnet_kernel<<<NBLK, 256>>>(img, W_ih, b_ih, b_hh, (float*)d_out);
}

// round 15
// speedup vs baseline: 1.0582x; 1.0039x over previous
#include <cuda_runtime.h>
#include <stdint.h>

#define HDIM 256
#define TS   256
#define BTOT 4096
#define BC   14
#define NP   7
#define NBLK ((BTOT + BC - 1) / BC)   // 293

// Repacked W: g_Wp[h4*256 + g] = float4{ W[g][4h4 .. 4h4+3] }  (coalesced across g)
__device__ float4 g_Wp[64 * 256];

__global__ void pack_w_kernel(const float* __restrict__ W) {
    int idx = blockIdx.x * blockDim.x + threadIdx.x;   // 0..16383
    int h4 = idx >> 8, gg = idx & 255;
    const float4* Wv = (const float4*)W;
    g_Wp[idx] = Wv[gg * 64 + h4];
}

// Threefry-2x32, 20 rounds — matches jax._src.prng.threefry2x32 exactly.
__device__ __forceinline__ uint2 tf2x32(uint32_t k0, uint32_t k1, uint32_t c0, uint32_t c1) {
    uint32_t ks2 = k0 ^ k1 ^ 0x1BD11BDAu;
    uint32_t x0 = c0 + k0, x1 = c1 + k1;
#define TFR(r) { x0 += x1; x1 = __funnelshift_l(x1, x1, r); x1 ^= x0; }
    TFR(13) TFR(15) TFR(26) TFR(6)
    x0 += k1;  x1 += ks2 + 1u;
    TFR(17) TFR(29) TFR(16) TFR(24)
    x0 += ks2; x1 += k0 + 2u;
    TFR(13) TFR(15) TFR(26) TFR(6)
    x0 += k0;  x1 += k1 + 3u;
    TFR(17) TFR(29) TFR(16) TFR(24)
    x0 += k1;  x1 += ks2 + 4u;
    TFR(13) TFR(15) TFR(26) TFR(6)
    x0 += ks2; x1 += k0 + 5u;
#undef TFR
    return make_uint2(x0, x1);
}

// jax.random.normal, threefry-partitionable path (default since JAX 0.4.36):
// bits[j] = x0 ^ x1 of threefry(key, (hi=0, lo=j)); uniform in [nextafter(-1,0), 1); sqrt(2)*erfinv.
__device__ __forceinline__ float jax_normal(uint2 key, uint32_t j) {
    uint2 r = tf2x32(key.x, key.y, 0u, j);
    uint32_t bits = r.x ^ r.y;
    float f = __uint_as_float((bits >> 9) | 0x3F800000u) - 1.0f;
    const float LO = -0.99999994f;               // nextafter(-1, 0)
    float u = fmaxf(LO, fmaf(f, 2.0f, LO));      // (hi-lo) rounds to 2.0f in fp32
    return 1.41421356f * erfinvf(u);
}

#define FMA2(d, a, b)     asm("fma.rn.f32x2 %0, %1, %2, %0;" : "+l"(d) : "l"(a), "l"(b))
#define PACK2(out, lo, hi) asm("mov.b64 %0, {%1, %2};" : "=l"(out) : "r"(lo), "r"(hi))
#define UNPACK2(lo, hi, in) asm("mov.b64 {%0, %1}, %2;" : "=r"(lo), "=r"(hi) : "l"(in))

__global__ __launch_bounds__(256, 2)
void drnet_kernel(const float* __restrict__ img, const float* __restrict__ W_ih,
                  const float* __restrict__ b_ih, const float* __restrict__ b_hh,
                  float* __restrict__ out) {
    // latent stored pair-interleaved for packed f32x2 math: Lp[p][h][j] = latent[2p+j][h]
    __shared__ __align__(16) float Lp[NP][HDIM][2];
    __shared__ float Xs[BC][TS];
    __shared__ uint2 Ks[TS];

    const int g = threadIdx.x;          // output feature
    const int base = blockIdx.x * BC;   // first batch row of this CTA

    // per-step keys: key_t = threefry((0,42), (0,t))  [partitionable split]
    Ks[g] = tf2x32(0u, 42u, 0u, (uint32_t)g);

    #pragma unroll
    for (int i = 0; i < BC; ++i) {
        int b = base + i; if (b >= BTOT) b = BTOT - 1;   // clamp (dupes never stored)
        Xs[i][g] = img[b * TS + g];                       // coalesced (g == t index here)
    }
    #pragma unroll
    for (int p = 0; p < NP; ++p) { Lp[p][g][0] = 0.f; Lp[p][g][1] = 0.f; }

    const float wih  = W_ih[g];
    const float bsum = b_ih[g] + b_hh[g];
    __syncthreads();

    for (int t = 0; t < TS; ++t) {
        const float a = (float)(257 - t) / 257.0f;        // a_t = (T - t + 1)/(T+1)
        const float sigma = sqrtf(a * (1.0f - a));
        const uint2 key = Ks[t];

        // acc[p] holds {arg(2p), arg(2p+1)} packed; init = x*w_ih + (b_ih + b_hh)
        unsigned long long acc[NP];
        #pragma unroll
        for (int p = 0; p < NP; ++p) {
            float alo = fmaf(Xs[2*p][t],   wih, bsum);
            float ahi = fmaf(Xs[2*p+1][t], wih, bsum);
            PACK2(acc[p], __float_as_uint(alo), __float_as_uint(ahi));
        }

        // matvec: acc[p] += sum_h W[g][h] * latent[{2p,2p+1}][h]  via packed fma.rn.f32x2
        float4 w4 = g_Wp[g];
        #pragma unroll 2
        for (int h4 = 0; h4 < 64; ++h4) {
            float4 wn = g_Wp[(((h4 + 1) & 63) << 8) + g];   // prefetch next
            unsigned long long wx, wy, wz, ww;
            PACK2(wx, __float_as_uint(w4.x), __float_as_uint(w4.x));
            PACK2(wy, __float_as_uint(w4.y), __float_as_uint(w4.y));
            PACK2(wz, __float_as_uint(w4.z), __float_as_uint(w4.z));
            PACK2(ww, __float_as_uint(w4.w), __float_as_uint(w4.w));
            #pragma unroll
            for (int p = 0; p < NP; ++p) {
                const ulonglong2* lp = (const ulonglong2*)&Lp[p][h4 * 4][0]; // broadcast LDS
                ulonglong2 l01 = lp[0];   // pairs for h=4h4, 4h4+1
                ulonglong2 l23 = lp[1];   // pairs for h=4h4+2, 4h4+3
                FMA2(acc[p], wx, l01.x);
                FMA2(acc[p], wy, l01.y);
                FMA2(acc[p], wz, l23.x);
                FMA2(acc[p], ww, l23.y);
            }
            w4 = wn;
        }

        // tanh + noise (does not touch Lp)
        float hv[BC], nz[BC];
        #pragma unroll
        for (int p = 0; p < NP; ++p) {
            uint32_t alo, ahi;
            UNPACK2(alo, ahi, acc[p]);
            hv[2*p]   = tanhf(__uint_as_float(alo));
            hv[2*p+1] = tanhf(__uint_as_float(ahi));
            nz[2*p]   = jax_normal(key, (uint32_t)((base + 2*p)     * HDIM + g));
            nz[2*p+1] = jax_normal(key, (uint32_t)((base + 2*p + 1) * HDIM + g));
        }

        __syncthreads();   // all matvec reads of Lp complete before updates
        #pragma unroll
        for (int p = 0; p < NP; ++p) {
            // latent = ((latent + x) + h) + sigma * (0.1 * normal)  — reference op order
            float l0 = Lp[p][g][0], l1 = Lp[p][g][1];
            l0 = l0 + Xs[2*p][t];   l0 = l0 + hv[2*p];   l0 = l0 + sigma * (0.1f * nz[2*p]);
            l1 = l1 + Xs[2*p+1][t]; l1 = l1 + hv[2*p+1]; l1 = l1 + sigma * (0.1f * nz[2*p+1]);
            Lp[p][g][0] = l0; Lp[p][g][1] = l1;
        }
        __syncthreads();   // updates visible before next step's matvec
    }

    #pragma unroll
    for (int p = 0; p < NP; ++p) {
        int b0 = base + 2*p, b1 = b0 + 1;
        if (b0 < BTOT) out[b0 * HDIM + g] = Lp[p][g][0];
        if (b1 < BTOT) out[b1 * HDIM + g] = Lp[p][g][1];
    }
}

extern "C" void kernel_launch(void* const* d_in, const int* in_sizes, int n_in,
                              void* d_out, int out_size) {
    // metadata order: T (int scalar), flat_img, W_ih, W_hh, b_ih, b_hh.
    // Be robust to T being absent: last 5 inputs are the arrays.
    int o = (n_in >= 6) ? (n_in - 5) : 0;
    const float* img  = (const float*)d_in[o + 0];
    const float* W_ih = (const float*)d_in[o + 1];
    const float* W_hh = (const float*)d_in[o + 2];
    const float* b_ih = (const float*)d_in[o + 3];
    const float* b_hh = (const float*)d_in[o + 4];

    pack_w_kernel<<<64, 256>>>(W_hh);
    drnet_kernel<<<NBLK, 256>>>(img, W_ih, b_ih, b_hh, (float*)d_out);
}

// round 16
// speedup vs baseline: 1.3188x; 1.2463x over previous
#include <cuda_runtime.h>
#include <stdint.h>

#define HDIM 256
#define TS   256
#define BTOT 4096
#define BC   28                        // batch rows per CTA (14 pairs)
#define NBLK ((BTOT + BC - 1) / BC)    // 147 CTAs ~= 1 per SM

// W split into even/odd-g planes so each thread (q) gets coalesced 16B loads
// for both of its output features g0=2q, g1=2q+1:
//   g_WpA[h4*128 + q] = float4{ W[2q  ][4h4 .. 4h4+3] }
//   g_WpB[h4*128 + q] = float4{ W[2q+1][4h4 .. 4h4+3] }
__device__ float4 g_WpA[64 * 128];
__device__ float4 g_WpB[64 * 128];

__global__ void pack_w_kernel(const float* __restrict__ W) {
    int idx = blockIdx.x * blockDim.x + threadIdx.x;   // 0..16383
    int h4 = idx >> 8, g = idx & 255;
    float4 v = ((const float4*)W)[g * 64 + h4];
    int q = g >> 1;
    if (g & 1) g_WpB[(h4 << 7) + q] = v;
    else       g_WpA[(h4 << 7) + q] = v;
}

// Threefry-2x32, 20 rounds — matches jax._src.prng.threefry2x32 exactly.
__device__ __forceinline__ uint2 tf2x32(uint32_t k0, uint32_t k1, uint32_t c0, uint32_t c1) {
    uint32_t ks2 = k0 ^ k1 ^ 0x1BD11BDAu;
    uint32_t x0 = c0 + k0, x1 = c1 + k1;
#define TFR(r) { x0 += x1; x1 = __funnelshift_l(x1, x1, r); x1 ^= x0; }
    TFR(13) TFR(15) TFR(26) TFR(6)
    x0 += k1;  x1 += ks2 + 1u;
    TFR(17) TFR(29) TFR(16) TFR(24)
    x0 += ks2; x1 += k0 + 2u;
    TFR(13) TFR(15) TFR(26) TFR(6)
    x0 += k0;  x1 += k1 + 3u;
    TFR(17) TFR(29) TFR(16) TFR(24)
    x0 += k1;  x1 += ks2 + 4u;
    TFR(13) TFR(15) TFR(26) TFR(6)
    x0 += ks2; x1 += k0 + 5u;
#undef TFR
    return make_uint2(x0, x1);
}

// jax.random.normal, threefry-partitionable path (verified bit-matching, rel_err 3e-5).
__device__ __forceinline__ float jax_normal(uint2 key, uint32_t j) {
    uint2 r = tf2x32(key.x, key.y, 0u, j);
    uint32_t bits = r.x ^ r.y;
    float f = __uint_as_float((bits >> 9) | 0x3F800000u) - 1.0f;
    const float LO = -0.99999994f;               // nextafter(-1, 0)
    float u = fmaxf(LO, fmaf(f, 2.0f, LO));
    return 1.41421356f * erfinvf(u);
}

#define FMA2(d, a, b)      asm("fma.rn.f32x2 %0, %1, %2, %0;" : "+l"(d) : "l"(a), "l"(b))
#define PACK2(out, lo, hi) asm("mov.b64 %0, {%1, %2};" : "=l"(out) : "r"(lo), "r"(hi))
#define UNPACK2(lo, hi, in) asm("mov.b64 {%0, %1}, %2;" : "=r"(lo), "=r"(hi) : "l"(in))
#define DUP2(out, v)       PACK2(out, __float_as_uint(v), __float_as_uint(v))

// One h4 slice: 8 FMA2 per pair p, serving BOTH g0 and g1 from one latent load pair.
__device__ __forceinline__ void math4(unsigned long long* accA, unsigned long long* accB,
                                      const float (*Lp)[HDIM][2], int p0, int h4,
                                      float4 wa, float4 wb) {
    unsigned long long ax, ay, az, aw, bx, by, bz, bw;
    DUP2(ax, wa.x); DUP2(ay, wa.y); DUP2(az, wa.z); DUP2(aw, wa.w);
    DUP2(bx, wb.x); DUP2(by, wb.y); DUP2(bz, wb.z); DUP2(bw, wb.w);
    #pragma unroll
    for (int p = 0; p < 7; ++p) {
        const ulonglong2* lptr = (const ulonglong2*)&Lp[p0 + p][h4 * 4][0];  // broadcast LDS
        ulonglong2 l01 = lptr[0];   // pairs {b0,b1} for h = 4h4, 4h4+1
        ulonglong2 l23 = lptr[1];   // pairs for h = 4h4+2, 4h4+3
        FMA2(accA[p], ax, l01.x);  FMA2(accB[p], bx, l01.x);
        FMA2(accA[p], ay, l01.y);  FMA2(accB[p], by, l01.y);
        FMA2(accA[p], az, l23.x);  FMA2(accB[p], bz, l23.x);
        FMA2(accA[p], aw, l23.y);  FMA2(accB[p], bw, l23.y);
    }
}

__global__ __launch_bounds__(256, 1)
void drnet_kernel(const float* __restrict__ img, const float* __restrict__ W_ih,
                  const float* __restrict__ b_ih, const float* __restrict__ b_hh,
                  float* __restrict__ out) {
    extern __shared__ float sm[];
    // Lp[pair][h][j] = latent[base + 2*pair + j][h]   (28 KB)
    float (*Lp)[HDIM][2] = (float (*)[HDIM][2])sm;
    // Xp[pair][t][j]   = x[base + 2*pair + j][t]      (28 KB)
    float (*Xp)[TS][2]   = (float (*)[TS][2])(sm + 14 * HDIM * 2);
    uint2* Ks            = (uint2*)(sm + 14 * HDIM * 2 + 14 * TS * 2);   // 2 KB

    const int t    = threadIdx.x;
    const int q    = t & 127;          // thread handles g0 = 2q, g1 = 2q+1
    const int half = t >> 7;           // pairs [7*half, 7*half+7)
    const int p0   = 7 * half;
    const int g0   = 2 * q;
    const int base = blockIdx.x * BC;

    Ks[t] = tf2x32(0u, 42u, 0u, (uint32_t)t);   // per-step split keys

    #pragma unroll
    for (int i = 0; i < BC; ++i) {
        int b = base + i; if (b >= BTOT) b = BTOT - 1;   // clamp (never stored)
        Xp[i >> 1][t][i & 1] = img[b * TS + t];           // coalesced over t
    }
    for (int i = t; i < 14 * HDIM * 2; i += 256) sm[i] = 0.0f;

    const float wih0  = W_ih[g0],            wih1  = W_ih[g0 + 1];
    const float bsum0 = b_ih[g0] + b_hh[g0], bsum1 = b_ih[g0 + 1] + b_hh[g0 + 1];
    __syncthreads();

    for (int st = 0; st < TS; ++st) {
        const float a     = (float)(257 - st) / 257.0f;   // a_t = (T - t + 1)/(T+1)
        const float sigma = sqrtf(a * (1.0f - a));
        const uint2 key   = Ks[st];

        // accX[p] = packed {arg(b0), arg(b1)} for feature gX; init x*w_ih + (b_ih+b_hh)
        unsigned long long accA[7], accB[7];
        #pragma unroll
        for (int p = 0; p < 7; ++p) {
            float2 xv = *(const float2*)&Xp[p0 + p][st][0];
            PACK2(accA[p], __float_as_uint(fmaf(xv.x, wih0, bsum0)),
                           __float_as_uint(fmaf(xv.y, wih0, bsum0)));
            PACK2(accB[p], __float_as_uint(fmaf(xv.x, wih1, bsum1)),
                           __float_as_uint(fmaf(xv.y, wih1, bsum1)));
        }

        // matvec over h, depth-2 W prefetch (covers L2 latency at 2 warps/SMSP)
        float4 wA0 = g_WpA[q],       wB0 = g_WpB[q];
        float4 wA1 = g_WpA[128 + q], wB1 = g_WpB[128 + q];
        #pragma unroll 1
        for (int h4 = 0; h4 < 64; h4 += 2) {
            int n0 = ((h4 + 2) & 63) << 7, n1 = ((h4 + 3) & 63) << 7;
            float4 nA0 = g_WpA[n0 + q], nB0 = g_WpB[n0 + q];
            float4 nA1 = g_WpA[n1 + q], nB1 = g_WpB[n1 + q];
            math4(accA, accB, Lp, p0, h4,     wA0, wB0);
            math4(accA, accB, Lp, p0, h4 + 1, wA1, wB1);
            wA0 = nA0; wB0 = nB0; wA1 = nA1; wB1 = nB1;
        }

        // tanh + noise + new latent (reads of Lp finish before the sync below)
        float4 nl[7];
        #pragma unroll
        for (int p = 0; p < 7; ++p) {
            int P = p0 + p;
            uint32_t alo, ahi, blo, bhi;
            UNPACK2(alo, ahi, accA[p]);
            UNPACK2(blo, bhi, accB[p]);
            float2 xv = *(const float2*)&Xp[P][st][0];
            float4 lv = *(const float4*)&Lp[P][g0][0];   // {b0g0, b1g0, b0g1, b1g1}
            uint32_t j00 = (uint32_t)(base + 2 * P) * HDIM + (uint32_t)g0;
            float n00 = jax_normal(key, j00);
            float n10 = jax_normal(key, j00 + HDIM);
            float n01 = jax_normal(key, j00 + 1);
            float n11 = jax_normal(key, j00 + HDIM + 1);
            // latent = ((latent + x) + h) + sigma * (0.1 * normal)  — reference order
            nl[p].x = ((lv.x + xv.x) + tanhf(__uint_as_float(alo))) + sigma * (0.1f * n00);
            nl[p].y = ((lv.y + xv.y) + tanhf(__uint_as_float(ahi))) + sigma * (0.1f * n10);
            nl[p].z = ((lv.z + xv.x) + tanhf(__uint_as_float(blo))) + sigma * (0.1f * n01);
            nl[p].w = ((lv.w + xv.y) + tanhf(__uint_as_float(bhi))) + sigma * (0.1f * n11);
        }

        __syncthreads();   // all matvec/latent reads complete before updates
        #pragma unroll
        for (int p = 0; p < 7; ++p)
            *(float4*)&Lp[p0 + p][g0][0] = nl[p];   // STS.128, conflict-free (stride 16B)
        __syncthreads();   // updates visible before next step's matvec
    }

    #pragma unroll
    for (int p = 0; p < 7; ++p) {
        int P = p0 + p, b0 = base + 2 * P;
        float4 lv = *(const float4*)&Lp[P][g0][0];
        if (b0 < BTOT)     { out[b0 * HDIM + g0] = lv.x;  out[b0 * HDIM + g0 + 1] = lv.z; }
        if (b0 + 1 < BTOT) { out[(b0 + 1) * HDIM + g0] = lv.y;
                             out[(b0 + 1) * HDIM + g0 + 1] = lv.w; }
    }
}

extern "C" void kernel_launch(void* const* d_in, const int* in_sizes, int n_in,
                              void* d_out, int out_size) {
    // metadata order: T (int scalar), flat_img, W_ih, W_hh, b_ih, b_hh.
    int o = (n_in >= 6) ? (n_in - 5) : 0;
    const float* img  = (const float*)d_in[o + 0];
    const float* W_ih = (const float*)d_in[o + 1];
    const float* W_hh = (const float*)d_in[o + 2];
    const float* b_ih = (const float*)d_in[o + 3];
    const float* b_hh = (const float*)d_in[o + 4];

    const int smem_bytes = (14 * HDIM * 2 + 14 * TS * 2 + TS * 2) * (int)sizeof(float); // 59392
    cudaFuncSetAttribute(drnet_kernel, cudaFuncAttributeMaxDynamicSharedMemorySize, smem_bytes);

    pack_w_kernel<<<64, 256>>>(W_hh);
    drnet_kernel<<<NBLK, 256, smem_bytes>>>(img, W_ih, b_ih, b_hh, (float*)d_out);
}